// round 2
// baseline (speedup 1.0000x reference)
#include <cuda_runtime.h>

#define BB 64
#define CC 768
#define HW 24
#define HID 768
#define KS 12      // K splits
#define KC 64      // K chunk (KS*KC = 768)

typedef unsigned long long ull;

// ---------------- device scratch ----------------
__device__ float g_wx[BB][16];
__device__ float g_wy[BB][16];
__device__ int   g_wlo[BB], g_wlen[BB], g_hlo[BB], g_hlen[BB];
__device__ ull   g_featp[BB * CC];     // pooled feat, packed (a,a)
__device__ ull   g_actp[BB * HID];     // layer-1 activation, packed (a,a)
__device__ float g_p1[KS][BB * HID];   // layer-1 K-split partials
__device__ float g_p2[KS][BB * HID];   // layer-2 K-split partials

// ---------------- packed fp32 helpers ----------------
__device__ __forceinline__ ull ffma2(ull a, ull b, ull c) {
    ull d;
    asm("fma.rn.f32x2 %0, %1, %2, %3;" : "=l"(d) : "l"(a), "l"(b), "l"(c));
    return d;
}
__device__ __forceinline__ ull dup2(float x) {
    ull d;
    asm("mov.b64 %0, {%1, %1};" : "=l"(d) : "f"(x));
    return d;
}

// ---------------- hat CDF ----------------
__device__ __forceinline__ float hat_cdf(float t) {
    if (t <= -1.f) return 0.f;
    if (t <= 0.f) { float u = t + 1.f; return 0.5f * u * u; }
    if (t <= 1.f) { float u = 1.f - t; return 1.f - 0.5f * u * u; }
    return 1.f;
}

// ---------------- kernel 1: per-batch telescoped box weights ----------------
__global__ void prep_kernel(const float* __restrict__ sb) {
    int b = threadIdx.x;
    if (b >= BB) return;
    float x0 = sb[b * 4 + 0] * (float)HW;
    float y0 = sb[b * 4 + 1] * (float)HW;
    float x1 = sb[b * 4 + 2] * (float)HW;
    float y1 = sb[b * 4 + 3] * (float)HW;
    float scale = 1.f / ((x1 - x0) * (y1 - y0));

    int wlo = max(0, (int)floorf(x0 - 1.f) + 1);
    int whi = min(HW - 1, (int)ceilf(x1 + 1.f) - 1);
    int hlo = max(0, (int)floorf(y0 - 1.f) + 1);
    int hhi = min(HW - 1, (int)ceilf(y1 + 1.f) - 1);
    g_wlo[b] = wlo; g_wlen[b] = whi - wlo + 1;
    g_hlo[b] = hlo; g_hlen[b] = hhi - hlo + 1;

    for (int i = 0; i <= whi - wlo; i++) {
        float c = (float)(wlo + i);
        g_wx[b][i] = hat_cdf(x1 - c) - hat_cdf(x0 - c);
    }
    for (int i = 0; i <= hhi - hlo; i++) {
        float c = (float)(hlo + i);
        g_wy[b][i] = (hat_cdf(y1 - c) - hat_cdf(y0 - c)) * scale;
    }
}

// ---------------- kernel 2: sparse weighted pooling -> g_featp ----------------
__global__ __launch_bounds__(256) void pool_kernel(const float* __restrict__ X) {
    __shared__ float s_wprod[256];
    __shared__ int   s_off[256];

    const int b = blockIdx.y;
    const int t = threadIdx.x;
    const int wlen = g_wlen[b], hlen = g_hlen[b];
    const int wlo  = g_wlo[b],  hlo  = g_hlo[b];
    const int n = wlen * hlen;

    for (int i = t; i < n; i += 256) {
        int h = i / wlen;
        int w = i - h * wlen;
        s_wprod[i] = g_wy[b][h] * g_wx[b][w];
        s_off[i]   = (hlo + h) * HW + (wlo + w);
    }
    __syncthreads();

    const int wid = t >> 5, lane = t & 31;
    const int cbase = blockIdx.x * 96 + wid * 12;
    for (int j = 0; j < 12; j++) {
        int c = cbase + j;
        const float* xp = X + (size_t)(b * CC + c) * (HW * HW);
        float acc = 0.f;
        for (int i = lane; i < n; i += 32)
            acc = fmaf(s_wprod[i], __ldg(xp + s_off[i]), acc);
        #pragma unroll
        for (int s = 16; s; s >>= 1) acc += __shfl_xor_sync(0xffffffffu, acc, s);
        if (lane == 0) g_featp[b * CC + c] = dup2(acc);
    }
}

// ---------------- GEMM: C_part = A * W over a K chunk --------------------
// grid (12, 2, 12): x = 64-col tile, y = 32-row tile, z = K chunk.
// block 128 = 4 warps; warp = 8 rows x 64 cols (lane = 2 cols, f32x2).
__global__ __launch_bounds__(128) void gemm_kernel(const ull* __restrict__ A,
                                                   const float* __restrict__ W,
                                                   float* __restrict__ P) {
    __shared__ ull As[32 * KC];   // [row][k] packed (a,a), 16 KB

    const int t  = threadIdx.x;
    const int r0b = blockIdx.y * 32;
    const int c0  = blockIdx.x * 64;
    const int k0  = blockIdx.z * KC;

    // A tile: rows r0b..r0b+31, k0..k0+63.  thread: row = t>>2, pair-group kp = t&3,
    // covers k = 2*kp + 8*i (staggered to limit STS bank conflicts).
    {
        const int row = t >> 2, kp = t & 3;
        const ull* src = A + (size_t)(r0b + row) * HID + k0 + 2 * kp;
        ull* dst = As + row * KC + 2 * kp;
        #pragma unroll
        for (int i = 0; i < 8; i++) {
            ulonglong2 v = *(const ulonglong2*)(src + 8 * i);
            *(ulonglong2*)(dst + 8 * i) = v;
        }
    }
    __syncthreads();

    const int wid = t >> 5, lane = t & 31;
    const ull* arow = As + (wid * 8) * KC;
    const float* wp = W + (size_t)k0 * HID + c0 + lane * 2;

    ull acc[8];
    #pragma unroll
    for (int r = 0; r < 8; r++) acc[r] = 0ull;

    #pragma unroll 4
    for (int k = 0; k < KC; k += 2) {
        ull w0 = *(const ull*)(wp + (size_t)k * HID);
        ull w1 = *(const ull*)(wp + (size_t)(k + 1) * HID);
        #pragma unroll
        for (int r = 0; r < 8; r++) {
            ulonglong2 a2 = *(const ulonglong2*)(arow + r * KC + k);
            acc[r] = ffma2(a2.x, w0, acc[r]);
            acc[r] = ffma2(a2.y, w1, acc[r]);
        }
    }

    float* op = P + (size_t)blockIdx.z * (BB * HID) + (size_t)r0b * HID + c0 + lane * 2;
    #pragma unroll
    for (int r = 0; r < 8; r++)
        *(ull*)(op + (size_t)(wid * 8 + r) * HID) = acc[r];
}

// ---------------- combine: sum K-split partials + bias + relu + pack ----------
__global__ __launch_bounds__(256) void combine_kernel(const float* __restrict__ bias) {
    const int e = blockIdx.x * 256 + threadIdx.x;   // 0..49151
    const int c = e % HID;
    float s = bias[c];
    #pragma unroll
    for (int z = 0; z < KS; z++) s += g_p1[z][e];
    g_actp[e] = dup2(fmaxf(s, 0.f));
}

// ---------------- final: combine layer-2 partials + bias + relu + dot w3 ------
__global__ __launch_bounds__(256) void final_kernel(
    const float* __restrict__ b2, const float* __restrict__ w3,
    const float* __restrict__ b3, float* __restrict__ out)
{
    __shared__ float red[8];
    const int b = blockIdx.x, t = threadIdx.x;
    float acc = 0.f;
    for (int k = t; k < HID; k += 256) {
        const int idx = b * HID + k;
        float s = b2[k];
        #pragma unroll
        for (int z = 0; z < KS; z++) s += g_p2[z][idx];
        acc = fmaf(fmaxf(s, 0.f), w3[k], acc);
    }
    #pragma unroll
    for (int s = 16; s; s >>= 1) acc += __shfl_xor_sync(0xffffffffu, acc, s);
    if ((t & 31) == 0) red[t >> 5] = acc;
    __syncthreads();
    if (t < 8) {
        acc = red[t];
        #pragma unroll
        for (int s = 4; s; s >>= 1) acc += __shfl_xor_sync(0xffu, acc, s);
        if (t == 0) out[b] = acc + b3[0];
    }
}

// ---------------- launch ----------------
extern "C" void kernel_launch(void* const* d_in, const int* in_sizes, int n_in,
                              void* d_out, int out_size) {
    const float* X  = (const float*)d_in[0];
    const float* sb = (const float*)d_in[1];
    const float* w1 = (const float*)d_in[2];
    const float* b1 = (const float*)d_in[3];
    const float* w2 = (const float*)d_in[4];
    const float* b2 = (const float*)d_in[5];
    const float* w3 = (const float*)d_in[6];
    const float* b3 = (const float*)d_in[7];
    float* out = (float*)d_out;

    ull* featp; cudaGetSymbolAddress((void**)&featp, g_featp);
    ull* actp;  cudaGetSymbolAddress((void**)&actp,  g_actp);
    float* p1;  cudaGetSymbolAddress((void**)&p1, g_p1);
    float* p2;  cudaGetSymbolAddress((void**)&p2, g_p2);

    prep_kernel<<<1, 64>>>(sb);
    pool_kernel<<<dim3(8, 64), 256>>>(X);
    dim3 g(12, 2, 12);
    gemm_kernel<<<g, 128>>>(featp, w1, p1);
    combine_kernel<<<192, 256>>>(b1);
    gemm_kernel<<<g, 128>>>(actp, w2, p2);
    final_kernel<<<64, 256>>>(b2, w3, b3, out);
}

// round 3
// speedup vs baseline: 1.0485x; 1.0485x over previous
#include <cuda_runtime.h>

typedef unsigned long long ull;
typedef unsigned int uint;

#define BB   64
#define CC   768
#define HW   24
#define NPIX 576
#define HID  768
#define NB   144      // grid size; must be <= 148 for co-residency
#define KSPL 6        // K splits per GEMM
#define KC   128      // K chunk  (KSPL*KC = 768)
#define CHUNK 342     // pool/combine elements per block (144*342 >= 49152)

// ---------------- device scratch ----------------
__device__ __align__(16) ull   g_featp[BB * CC];     // pooled feat, packed (a,a)
__device__ __align__(16) ull   g_actp[BB * HID];     // layer-1 act, packed (a,a)
__device__ __align__(16) float g_p1[KSPL][BB * HID];
__device__ __align__(16) float g_p2[KSPL][BB * HID];
__device__ int           g_count = 0;
__device__ volatile int  g_sense = 0;

// ---------------- packed fp32 helpers ----------------
__device__ __forceinline__ ull ffma2(ull a, ull b, ull c) {
    ull d;
    asm("fma.rn.f32x2 %0, %1, %2, %3;" : "=l"(d) : "l"(a), "l"(b), "l"(c));
    return d;
}
__device__ __forceinline__ ull dup2(float x) {
    ull d;
    asm("mov.b64 %0, {%1, %1};" : "=l"(d) : "f"(x));
    return d;
}

__device__ __forceinline__ float hat_cdf(float t) {
    if (t <= -1.f) return 0.f;
    if (t <= 0.f) { float u = t + 1.f; return 0.5f * u * u; }
    if (t <= 1.f) { float u = 1.f - t; return 1.f - 0.5f * u * u; }
    return 1.f;
}

// ---------------- grid-wide sense-reversing barrier ----------------
__device__ __forceinline__ void grid_sync(int ls) {
    __syncthreads();
    __threadfence();
    if (threadIdx.x == 0) {
        if (atomicAdd(&g_count, 1) == NB - 1) {
            g_count = 0;
            __threadfence();
            g_sense = ls;
        } else {
            while (g_sense != ls) { }
        }
    }
    __syncthreads();
    __threadfence();
}

// ---------------- shared scratch (aliased across phases) ----------------
__shared__ __align__(16) ull s_buf[32 * KC];   // 32 KB: GEMM A-tile / pool tables

// ---------------- GEMM phase: P[z] += A[32xKC] * W[KCx64] ----------------
__device__ __forceinline__ void gemm_phase(const ull* __restrict__ A,
                                           const float* __restrict__ W,
                                           float* __restrict__ P) {
    const int bid = blockIdx.x;
    const int x = bid % 12;           // col tile (64 cols)
    const int y = (bid / 12) % 2;     // row tile (32 rows)
    const int z = bid / 24;           // k chunk
    const int c0 = x * 64, r0 = y * 32, k0 = z * KC;
    const int t = threadIdx.x;

    // Load A tile: 32 rows x 128 k (packed ull), coalesced 128B per thread
    {
        const int row = t >> 3, seg = (t & 7) * 16;
        const ull* src = A + (size_t)(r0 + row) * HID + k0 + seg;
        ull* dst = s_buf + row * KC + seg;
        #pragma unroll
        for (int j = 0; j < 8; j++)
            ((ulonglong2*)dst)[j] = ((const ulonglong2*)src)[j];
    }
    __syncthreads();

    const int wid = t >> 5, lane = t & 31;
    const ull* ar = s_buf + (wid * 4) * KC;
    const float* wptr = W + (size_t)k0 * HID + c0 + lane * 2;

    ull acc0 = 0ull, acc1 = 0ull, acc2 = 0ull, acc3 = 0ull;

    #pragma unroll 4
    for (int k = 0; k < KC; k += 2) {
        ull w0 = *(const ull*)(wptr + (size_t)k * HID);
        ull w1 = *(const ull*)(wptr + (size_t)(k + 1) * HID);
        ulonglong2 a0 = *(const ulonglong2*)(ar + 0 * KC + k);
        ulonglong2 a1 = *(const ulonglong2*)(ar + 1 * KC + k);
        ulonglong2 a2 = *(const ulonglong2*)(ar + 2 * KC + k);
        ulonglong2 a3 = *(const ulonglong2*)(ar + 3 * KC + k);
        acc0 = ffma2(a0.x, w0, acc0); acc0 = ffma2(a0.y, w1, acc0);
        acc1 = ffma2(a1.x, w0, acc1); acc1 = ffma2(a1.y, w1, acc1);
        acc2 = ffma2(a2.x, w0, acc2); acc2 = ffma2(a2.y, w1, acc2);
        acc3 = ffma2(a3.x, w0, acc3); acc3 = ffma2(a3.y, w1, acc3);
    }

    float* op = P + (size_t)z * (BB * HID) + (size_t)(r0 + wid * 4) * HID + c0 + lane * 2;
    *(ull*)(op + 0 * HID) = acc0;
    *(ull*)(op + 1 * HID) = acc1;
    *(ull*)(op + 2 * HID) = acc2;
    *(ull*)(op + 3 * HID) = acc3;
}

// ---------------- the single fused kernel ----------------
__global__ __launch_bounds__(256) void fused_kernel(
    const float* __restrict__ X,  const float* __restrict__ sb,
    const float* __restrict__ w1, const float* __restrict__ b1,
    const float* __restrict__ w2, const float* __restrict__ b2,
    const float* __restrict__ w3, const float* __restrict__ b3,
    float* __restrict__ out)
{
    const int bid = blockIdx.x;
    const int t = threadIdx.x;
    const int wid = t >> 5, lane = t & 31;

    // ======== phase 0+1: box weights (local) + sparse pooling ========
    {
        const int s = bid * CHUNK;
        const int e = min(s + CHUNK, BB * CC);
        const int cnt = e - s;
        const int bfirst = s / CC;
        const int blast = (e - 1) / CC;

        // packed (wprod, off) tables: 2 batch slots x 256 entries
        ull* s_pk = s_buf;   // [2][256]
        int nq[2] = {0, 0};

        #pragma unroll
        for (int q = 0; q < 2; q++) {
            float wpv = 0.f;
            int offv = 0;
            int b = bfirst + q;
            if (b <= blast && b < BB) {
                float x0 = sb[b * 4 + 0] * (float)HW;
                float y0 = sb[b * 4 + 1] * (float)HW;
                float x1 = sb[b * 4 + 2] * (float)HW;
                float y1 = sb[b * 4 + 3] * (float)HW;
                float scale = 1.f / ((x1 - x0) * (y1 - y0));
                int wlo = max(0, (int)floorf(x0 - 1.f) + 1);
                int whi = min(HW - 1, (int)ceilf(x1 + 1.f) - 1);
                int hlo = max(0, (int)floorf(y0 - 1.f) + 1);
                int hhi = min(HW - 1, (int)ceilf(y1 + 1.f) - 1);
                int wlen = whi - wlo + 1, hlen = hhi - hlo + 1;
                int n = wlen * hlen;
                nq[q] = n;
                if (t < n) {
                    int h = t / wlen;
                    int w = t - h * wlen;
                    float wy = hat_cdf(y1 - (float)(hlo + h)) - hat_cdf(y0 - (float)(hlo + h));
                    float wx = hat_cdf(x1 - (float)(wlo + w)) - hat_cdf(x0 - (float)(wlo + w));
                    wpv = wy * wx * scale;
                    offv = (hlo + h) * HW + (wlo + w);
                }
            }
            s_pk[q * 256 + t] = ((ull)__float_as_uint(wpv) << 32) | (uint)offv;
        }
        __syncthreads();

        const int nmx = max(nq[0], nq[1]);

        // each warp: 4 channels concurrently
        for (int g = wid * 4; g < cnt; g += 32) {
            float acc[4] = {0.f, 0.f, 0.f, 0.f};
            const float* xp[4];
            int qof[4];
            #pragma unroll
            for (int j = 0; j < 4; j++) {
                int ci = (g + j < cnt) ? (g + j) : 0;
                int cg = s + ci;
                xp[j] = X + (size_t)cg * NPIX;
                qof[j] = ((cg / CC) - bfirst) * 256;
            }
            for (int i = lane; i < nmx; i += 32) {
                #pragma unroll
                for (int j = 0; j < 4; j++) {
                    ull p = s_pk[qof[j] + i];
                    float wv = __uint_as_float((uint)(p >> 32));
                    int off = (int)(uint)p;
                    acc[j] = fmaf(wv, __ldg(xp[j] + off), acc[j]);
                }
            }
            #pragma unroll
            for (int j = 0; j < 4; j++) {
                float a = acc[j];
                #pragma unroll
                for (int sh = 16; sh; sh >>= 1) a += __shfl_xor_sync(0xffffffffu, a, sh);
                if (lane == 0 && g + j < cnt) g_featp[s + g + j] = dup2(a);
            }
        }
    }

    grid_sync(1);

    // ======== phase 2: GEMM 1 ========
    gemm_phase(g_featp, w1, &g_p1[0][0]);

    grid_sync(0);

    // ======== phase 3: combine partials + bias + relu + pack ========
    {
        const int s = bid * CHUNK;
        const int e = min(s + CHUNK, BB * HID);
        for (int idx = s + t; idx < e; idx += 256) {
            int c = idx % HID;
            float v = b1[c];
            #pragma unroll
            for (int z = 0; z < KSPL; z++) v += g_p1[z][idx];
            g_actp[idx] = dup2(fmaxf(v, 0.f));
        }
    }

    grid_sync(1);

    // ======== phase 4: GEMM 2 ========
    gemm_phase(g_actp, w2, &g_p2[0][0]);

    grid_sync(0);

    // ======== phase 5: final combine + dot(w3) ========
    if (bid < BB) {
        float acc = 0.f;
        for (int k = t; k < HID; k += 256) {
            const int idx = bid * HID + k;
            float v = b2[k];
            #pragma unroll
            for (int z = 0; z < KSPL; z++) v += g_p2[z][idx];
            acc = fmaf(fmaxf(v, 0.f), w3[k], acc);
        }
        #pragma unroll
        for (int sh = 16; sh; sh >>= 1) acc += __shfl_xor_sync(0xffffffffu, acc, sh);
        float* red = (float*)s_buf;
        __syncthreads();
        if (lane == 0) red[wid] = acc;
        __syncthreads();
        if (t == 0) {
            float r = red[0] + red[1] + red[2] + red[3] +
                      red[4] + red[5] + red[6] + red[7];
            out[bid] = r + b3[0];
        }
    }
}

// ---------------- launch ----------------
extern "C" void kernel_launch(void* const* d_in, const int* in_sizes, int n_in,
                              void* d_out, int out_size) {
    const float* X  = (const float*)d_in[0];
    const float* sb = (const float*)d_in[1];
    const float* w1 = (const float*)d_in[2];
    const float* b1 = (const float*)d_in[3];
    const float* w2 = (const float*)d_in[4];
    const float* b2 = (const float*)d_in[5];
    const float* w3 = (const float*)d_in[6];
    const float* b3 = (const float*)d_in[7];
    float* out = (float*)d_out;

    fused_kernel<<<NB, 256>>>(X, sb, w1, b1, w2, b2, w3, b3, out);
}

// round 4
// speedup vs baseline: 1.5272x; 1.4565x over previous
#include <cuda_runtime.h>

typedef unsigned long long ull;
typedef unsigned int uint;

#define BB   64
#define CC   768
#define HW   24
#define NPIX 576
#define HID  768
#define NB   144        // blocks; <=148 so all co-resident (1 block/SM)
#define NT   512        // threads per block (16 warps)
#define NWARP (NB * (NT / 32))
#define KSPL 12         // K splits per GEMM
#define KC   64         // K chunk (KSPL*KC = 768)
#define TABS 228        // table stride per batch (ull entries), n <= 225
#define NITEM (BB * 96) // pool items: 64 batches x 96 groups of 8 channels
#define CHUNK 342       // combine elements per block (144*342 >= 49152)

// ---------------- device scratch ----------------
__device__ __align__(16) ull   g_featp[BB * CC];
__device__ __align__(16) ull   g_actp[BB * HID];
__device__ __align__(16) float g_p1[KSPL][BB * HID];
__device__ __align__(16) float g_p2[KSPL][BB * HID];
__device__ int           g_count = 0;
__device__ volatile int  g_sense = 0;

// ---------------- helpers ----------------
__device__ __forceinline__ ull ffma2(ull a, ull b, ull c) {
    ull d;
    asm("fma.rn.f32x2 %0, %1, %2, %3;" : "=l"(d) : "l"(a), "l"(b), "l"(c));
    return d;
}
__device__ __forceinline__ ull dup2(float x) {
    ull d;
    asm("mov.b64 %0, {%1, %1};" : "=l"(d) : "f"(x));
    return d;
}
__device__ __forceinline__ float hat_cdf(float t) {
    if (t <= -1.f) return 0.f;
    if (t <= 0.f) { float u = t + 1.f; return 0.5f * u * u; }
    if (t <= 1.f) { float u = 1.f - t; return 1.f - 0.5f * u * u; }
    return 1.f;
}

__device__ __forceinline__ void grid_sync(int ls) {
    __syncthreads();
    __threadfence();
    if (threadIdx.x == 0) {
        if (atomicAdd(&g_count, 1) == NB - 1) {
            g_count = 0;
            __threadfence();
            g_sense = ls;
        } else {
            while (g_sense != ls) { }
        }
    }
    __syncthreads();
    __threadfence();
}

// ---------------- GEMM phase: 64 rows x 64 cols x KC over k-chunk ----------
// bid -> x = bid%12 (col tile), z = bid/12 (k chunk). warp = 4 rows.
__device__ __forceinline__ void gemm_phase(ull* s_dyn,
                                           const ull* __restrict__ A,
                                           const float* __restrict__ W,
                                           float* __restrict__ P) {
    const int t = threadIdx.x;
    const int x = blockIdx.x % 12;
    const int z = blockIdx.x / 12;
    const int c0 = x * 64;
    const int k0 = z * KC;

    // A tile: 64 rows x 64 k (ull) = 32KB. thread: row = t>>3, 8 ull = 64B.
    {
        const int row = t >> 3, seg = (t & 7) * 8;
        const ull* src = A + (size_t)row * HID + k0 + seg;
        ull* dst = s_dyn + row * KC + seg;
        #pragma unroll
        for (int j = 0; j < 8; j += 2)
            *(ulonglong2*)(dst + j) = *(const ulonglong2*)(src + j);
    }
    __syncthreads();

    const int wid = t >> 5, lane = t & 31;
    const ull* ar = s_dyn + (wid * 4) * KC;
    const float* wptr = W + (size_t)k0 * HID + c0 + lane * 2;

    ull acc0 = 0ull, acc1 = 0ull, acc2 = 0ull, acc3 = 0ull;

    #pragma unroll 4
    for (int k = 0; k < KC; k += 2) {
        ull w0 = *(const ull*)(wptr + (size_t)k * HID);
        ull w1 = *(const ull*)(wptr + (size_t)(k + 1) * HID);
        ulonglong2 a0 = *(const ulonglong2*)(ar + 0 * KC + k);
        ulonglong2 a1 = *(const ulonglong2*)(ar + 1 * KC + k);
        ulonglong2 a2 = *(const ulonglong2*)(ar + 2 * KC + k);
        ulonglong2 a3 = *(const ulonglong2*)(ar + 3 * KC + k);
        acc0 = ffma2(a0.x, w0, acc0); acc0 = ffma2(a0.y, w1, acc0);
        acc1 = ffma2(a1.x, w0, acc1); acc1 = ffma2(a1.y, w1, acc1);
        acc2 = ffma2(a2.x, w0, acc2); acc2 = ffma2(a2.y, w1, acc2);
        acc3 = ffma2(a3.x, w0, acc3); acc3 = ffma2(a3.y, w1, acc3);
    }

    float* op = P + (size_t)z * (BB * HID) + (size_t)(wid * 4) * HID + c0 + lane * 2;
    *(ull*)(op + 0 * HID) = acc0;
    *(ull*)(op + 1 * HID) = acc1;
    *(ull*)(op + 2 * HID) = acc2;
    *(ull*)(op + 3 * HID) = acc3;
    __syncthreads();   // protect s_dyn before next phase reuses it
}

// ---------------- the single fused kernel ----------------
__global__ __launch_bounds__(NT, 1) void fused_kernel(
    const float* __restrict__ X,  const float* __restrict__ sb,
    const float* __restrict__ w1, const float* __restrict__ b1,
    const float* __restrict__ w2, const float* __restrict__ b2,
    const float* __restrict__ w3, const float* __restrict__ b3,
    float* __restrict__ out)
{
    extern __shared__ __align__(16) ull s_dyn[];   // 114KB tables / 32KB A-tile
    __shared__ int   s_n[BB];
    __shared__ float s_red[16];

    const int bid = blockIdx.x;
    const int t = threadIdx.x;
    const int wid = t >> 5, lane = t & 31;

    // ======== phase 0a: build all 64 weight tables in smem (redundant/block) ====
    for (int e = t; e < BB * TABS; e += NT) {
        const int b = e / TABS;
        const int i = e - b * TABS;
        float x0 = sb[b * 4 + 0] * (float)HW;
        float y0 = sb[b * 4 + 1] * (float)HW;
        float x1 = sb[b * 4 + 2] * (float)HW;
        float y1 = sb[b * 4 + 3] * (float)HW;
        float scale = 1.f / ((x1 - x0) * (y1 - y0));
        int wlo = max(0, (int)floorf(x0 - 1.f) + 1);
        int whi = min(HW - 1, (int)ceilf(x1 + 1.f) - 1);
        int hlo = max(0, (int)floorf(y0 - 1.f) + 1);
        int hhi = min(HW - 1, (int)ceilf(y1 + 1.f) - 1);
        int wlen = whi - wlo + 1;
        int n = wlen * (hhi - hlo + 1);
        if (i == 0) s_n[b] = n;
        if (i < n) {
            int h = i / wlen;
            int w = i - h * wlen;
            float wy = hat_cdf(y1 - (float)(hlo + h)) - hat_cdf(y0 - (float)(hlo + h));
            float wx = hat_cdf(x1 - (float)(wlo + w)) - hat_cdf(x0 - (float)(wlo + w));
            float wv = wy * wx * scale;
            int off = (hlo + h) * HW + (wlo + w);
            s_dyn[e] = ((ull)__float_as_uint(wv) << 32) | (uint)off;
        }
    }
    __syncthreads();

    // ======== phase 0b: pooling. item = (b, 8-channel group), warp-strided ====
    {
        const int wg = bid * (NT / 32) + wid;
        for (int it = wg; it < NITEM; it += NWARP) {
            const int b = it / 96;
            const int cg = it - b * 96;
            const int c0g = b * CC + cg * 8;
            const float* xbase = X + (size_t)c0g * NPIX;
            const int n = s_n[b];
            const ull* tab = s_dyn + b * TABS;

            float a0 = 0.f, a1 = 0.f, a2 = 0.f, a3 = 0.f;
            float a4 = 0.f, a5 = 0.f, a6 = 0.f, a7 = 0.f;
            for (int i = lane; i < n; i += 32) {
                ull p = tab[i];
                float wv = __uint_as_float((uint)(p >> 32));
                int off = (int)(uint)p;
                a0 = fmaf(wv, __ldg(xbase + 0 * NPIX + off), a0);
                a1 = fmaf(wv, __ldg(xbase + 1 * NPIX + off), a1);
                a2 = fmaf(wv, __ldg(xbase + 2 * NPIX + off), a2);
                a3 = fmaf(wv, __ldg(xbase + 3 * NPIX + off), a3);
                a4 = fmaf(wv, __ldg(xbase + 4 * NPIX + off), a4);
                a5 = fmaf(wv, __ldg(xbase + 5 * NPIX + off), a5);
                a6 = fmaf(wv, __ldg(xbase + 6 * NPIX + off), a6);
                a7 = fmaf(wv, __ldg(xbase + 7 * NPIX + off), a7);
            }
            #pragma unroll
            for (int sh = 16; sh; sh >>= 1) {
                a0 += __shfl_xor_sync(0xffffffffu, a0, sh);
                a1 += __shfl_xor_sync(0xffffffffu, a1, sh);
                a2 += __shfl_xor_sync(0xffffffffu, a2, sh);
                a3 += __shfl_xor_sync(0xffffffffu, a3, sh);
                a4 += __shfl_xor_sync(0xffffffffu, a4, sh);
                a5 += __shfl_xor_sync(0xffffffffu, a5, sh);
                a6 += __shfl_xor_sync(0xffffffffu, a6, sh);
                a7 += __shfl_xor_sync(0xffffffffu, a7, sh);
            }
            float v = a0;
            v = (lane == 1) ? a1 : v;
            v = (lane == 2) ? a2 : v;
            v = (lane == 3) ? a3 : v;
            v = (lane == 4) ? a4 : v;
            v = (lane == 5) ? a5 : v;
            v = (lane == 6) ? a6 : v;
            v = (lane == 7) ? a7 : v;
            if (lane < 8) g_featp[c0g + lane] = dup2(v);
        }
    }

    grid_sync(1);

    // ======== phase 1: GEMM 1 ========
    gemm_phase(s_dyn, g_featp, w1, &g_p1[0][0]);

    grid_sync(0);

    // ======== phase 2: combine partials + bias + relu + pack ========
    {
        const int s0 = bid * CHUNK;
        const int e0 = min(s0 + CHUNK, BB * HID);
        for (int idx = s0 + t; idx < e0; idx += NT) {
            const int c = idx % HID;
            float v = b1[c];
            #pragma unroll
            for (int z = 0; z < KSPL; z++) v += g_p1[z][idx];
            g_actp[idx] = dup2(fmaxf(v, 0.f));
        }
    }

    grid_sync(1);

    // ======== phase 3: GEMM 2 ========
    gemm_phase(s_dyn, g_actp, w2, &g_p2[0][0]);

    grid_sync(0);

    // ======== phase 4: final combine + dot(w3) ========
    if (bid < BB) {
        float acc = 0.f;
        for (int k = t; k < HID; k += NT) {
            const int idx = bid * HID + k;
            float v = b2[k];
            #pragma unroll
            for (int z = 0; z < KSPL; z++) v += g_p2[z][idx];
            acc = fmaf(fmaxf(v, 0.f), w3[k], acc);
        }
        #pragma unroll
        for (int sh = 16; sh; sh >>= 1) acc += __shfl_xor_sync(0xffffffffu, acc, sh);
        if (lane == 0) s_red[wid] = acc;
        __syncthreads();
        if (t == 0) {
            float r = 0.f;
            #pragma unroll
            for (int j = 0; j < 16; j++) r += s_red[j];
            out[bid] = r + b3[0];
        }
    }
}

// ---------------- launch ----------------
extern "C" void kernel_launch(void* const* d_in, const int* in_sizes, int n_in,
                              void* d_out, int out_size) {
    const float* X  = (const float*)d_in[0];
    const float* sb = (const float*)d_in[1];
    const float* w1 = (const float*)d_in[2];
    const float* b1 = (const float*)d_in[3];
    const float* w2 = (const float*)d_in[4];
    const float* b2 = (const float*)d_in[5];
    const float* w3 = (const float*)d_in[6];
    const float* b3 = (const float*)d_in[7];
    float* out = (float*)d_out;

    const int smem = BB * TABS * (int)sizeof(ull);   // 116736 B
    static int configured = 0;
    if (!configured) {
        cudaFuncSetAttribute(fused_kernel,
                             cudaFuncAttributeMaxDynamicSharedMemorySize, smem);
        configured = 1;
    }
    fused_kernel<<<NB, NT, smem>>>(X, sb, w1, b1, w2, b2, w3, b3, out);
}

// round 5
// speedup vs baseline: 1.7029x; 1.1150x over previous
#include <cuda_runtime.h>

typedef unsigned long long ull;
typedef unsigned int uint;

#define BB   64
#define CC   768
#define HW   24
#define NPIX 576
#define HID  768
#define NB   144        // blocks; <=148 so all co-resident
#define NT   512        // threads per block (16 warps)
#define NWARP (NB * (NT / 32))
#define KSPL 12         // K splits per GEMM
#define KC   64         // K chunk (KSPL*KC = 768)
#define TABV 80         // vec-table stride per batch (max n_vec = 70)
#define NITEM (BB * 96) // pool items: 64 batches x 96 groups of 8 channels
#define CHUNK 342       // combine elements per block

// ---------------- device scratch ----------------
__device__ __align__(16) ull   g_featp[BB * CC];
__device__ __align__(16) ull   g_actp[BB * HID];
__device__ __align__(16) float g_p1[KSPL][BB * HID];
__device__ __align__(16) float g_p2[KSPL][BB * HID];
__device__ int           g_count = 0;
__device__ volatile int  g_sense = 0;

// ---------------- packed fp32 helpers ----------------
__device__ __forceinline__ ull ffma2(ull a, ull b, ull c) {
    ull d;
    asm("fma.rn.f32x2 %0, %1, %2, %3;" : "=l"(d) : "l"(a), "l"(b), "l"(c));
    return d;
}
__device__ __forceinline__ ull fadd2(ull a, ull b) {
    ull d;
    asm("add.rn.f32x2 %0, %1, %2;" : "=l"(d) : "l"(a), "l"(b));
    return d;
}
__device__ __forceinline__ ull dup2(float x) {
    ull d;
    asm("mov.b64 %0, {%1, %1};" : "=l"(d) : "f"(x));
    return d;
}
__device__ __forceinline__ float hsum2(ull p) {
    return __uint_as_float((uint)p) + __uint_as_float((uint)(p >> 32));
}

__device__ __forceinline__ float hat_cdf(float t) {
    if (t <= -1.f) return 0.f;
    if (t <= 0.f) { float u = t + 1.f; return 0.5f * u * u; }
    if (t <= 1.f) { float u = 1.f - t; return 1.f - 0.5f * u * u; }
    return 1.f;
}

__device__ __forceinline__ void grid_sync(int ls) {
    __syncthreads();
    __threadfence();
    if (threadIdx.x == 0) {
        if (atomicAdd(&g_count, 1) == NB - 1) {
            g_count = 0;
            __threadfence();
            g_sense = ls;
        } else {
            while (g_sense != ls) { }
        }
    }
    __syncthreads();
    __threadfence();
}

// ---------------- GEMM phase: 64 rows x 64 cols x KC over k-chunk ----------
__device__ __forceinline__ void gemm_phase(ull* s_dyn,
                                           const ull* __restrict__ A,
                                           const float* __restrict__ W,
                                           float* __restrict__ P) {
    const int t = threadIdx.x;
    const int x = blockIdx.x % 12;
    const int z = blockIdx.x / 12;
    const int c0 = x * 64;
    const int k0 = z * KC;

    // A tile: 64 rows x 64 k (ull) = 32KB
    {
        const int row = t >> 3, seg = (t & 7) * 8;
        const ull* src = A + (size_t)row * HID + k0 + seg;
        ull* dst = s_dyn + row * KC + seg;
        #pragma unroll
        for (int j = 0; j < 8; j += 2)
            *(ulonglong2*)(dst + j) = *(const ulonglong2*)(src + j);
    }
    __syncthreads();

    const int wid = t >> 5, lane = t & 31;
    const ull* ar = s_dyn + (wid * 4) * KC;
    const float* wptr = W + (size_t)k0 * HID + c0 + lane * 2;

    ull acc0 = 0ull, acc1 = 0ull, acc2 = 0ull, acc3 = 0ull;

    #pragma unroll 4
    for (int k = 0; k < KC; k += 2) {
        ull w0 = *(const ull*)(wptr + (size_t)k * HID);
        ull w1 = *(const ull*)(wptr + (size_t)(k + 1) * HID);
        ulonglong2 a0 = *(const ulonglong2*)(ar + 0 * KC + k);
        ulonglong2 a1 = *(const ulonglong2*)(ar + 1 * KC + k);
        ulonglong2 a2 = *(const ulonglong2*)(ar + 2 * KC + k);
        ulonglong2 a3 = *(const ulonglong2*)(ar + 3 * KC + k);
        acc0 = ffma2(a0.x, w0, acc0); acc0 = ffma2(a0.y, w1, acc0);
        acc1 = ffma2(a1.x, w0, acc1); acc1 = ffma2(a1.y, w1, acc1);
        acc2 = ffma2(a2.x, w0, acc2); acc2 = ffma2(a2.y, w1, acc2);
        acc3 = ffma2(a3.x, w0, acc3); acc3 = ffma2(a3.y, w1, acc3);
    }

    float* op = P + (size_t)z * (BB * HID) + (size_t)(wid * 4) * HID + c0 + lane * 2;
    *(ull*)(op + 0 * HID) = acc0;
    *(ull*)(op + 1 * HID) = acc1;
    *(ull*)(op + 2 * HID) = acc2;
    *(ull*)(op + 3 * HID) = acc3;
    __syncthreads();
}

// ---------------- the single fused kernel ----------------
__global__ __launch_bounds__(NT, 1) void fused_kernel(
    const float* __restrict__ X,  const float* __restrict__ sb,
    const float* __restrict__ w1, const float* __restrict__ b1,
    const float* __restrict__ w2, const float* __restrict__ b2,
    const float* __restrict__ w3, const float* __restrict__ b3,
    float* __restrict__ out)
{
    // dynamic smem: [0, 81920) float4 weights; [81920, 102400) int offsets.
    // GEMM phases alias the first 32KB as the A tile.
    extern __shared__ __align__(16) ull s_dyn[];
    float4* s_w4 = (float4*)s_dyn;
    int*    s_off = (int*)(s_w4 + BB * TABV);
    __shared__ int   s_n[BB];
    __shared__ float s_red[16];

    const int bid = blockIdx.x;
    const int t = threadIdx.x;
    const int wid = t >> 5, lane = t & 31;

    // ======== phase 0a: build 64 vectorized weight tables in smem ========
    for (int e = t; e < BB * TABV; e += NT) {
        const int b = e / TABV;
        const int i = e - b * TABV;
        float x0 = sb[b * 4 + 0] * (float)HW;
        float y0 = sb[b * 4 + 1] * (float)HW;
        float x1 = sb[b * 4 + 2] * (float)HW;
        float y1 = sb[b * 4 + 3] * (float)HW;
        float scale = 1.f / ((x1 - x0) * (y1 - y0));
        int wlo = max(0, (int)floorf(x0 - 1.f) + 1);
        int whi = min(HW - 1, (int)ceilf(x1 + 1.f) - 1);
        int hlo = max(0, (int)floorf(y0 - 1.f) + 1);
        int hhi = min(HW - 1, (int)ceilf(y1 + 1.f) - 1);
        const int wv0 = wlo >> 2;
        const int nv = (whi >> 2) - wv0 + 1;      // vec4 segments per row
        const int n_vec = (hhi - hlo + 1) * nv;
        if (i == 0) s_n[b] = n_vec;
        if (i < n_vec) {
            int h = i / nv;
            int vs = i - h * nv;
            int wbase = (wv0 + vs) * 4;
            float wy = (hat_cdf(y1 - (float)(hlo + h)) -
                        hat_cdf(y0 - (float)(hlo + h))) * scale;
            float4 wv;
            wv.x = wy * (hat_cdf(x1 - (float)(wbase + 0)) - hat_cdf(x0 - (float)(wbase + 0)));
            wv.y = wy * (hat_cdf(x1 - (float)(wbase + 1)) - hat_cdf(x0 - (float)(wbase + 1)));
            wv.z = wy * (hat_cdf(x1 - (float)(wbase + 2)) - hat_cdf(x0 - (float)(wbase + 2)));
            wv.w = wy * (hat_cdf(x1 - (float)(wbase + 3)) - hat_cdf(x0 - (float)(wbase + 3)));
            s_w4[e] = wv;
            s_off[e] = (hlo + h) * HW + wbase;
        }
    }
    __syncthreads();

    // ======== phase 0b: pooling with vec4 gathers ========
    // item = (b, 8-channel group). warp = 4 subgroups of 8 lanes; each
    // subgroup owns 2 channels and strides entries by 8.
    {
        const int sub = lane >> 3;       // 0..3
        const int sl  = lane & 7;        // 0..7
        const int wg = bid * (NT / 32) + wid;
        for (int it = wg; it < NITEM; it += NWARP) {
            const int b = it / 96;
            const int cg = it - b * 96;
            const int c0g = b * CC + cg * 8;
            const int c = c0g + 2 * sub;
            const float* xb0 = X + (size_t)c * NPIX;
            const float* xb1 = xb0 + NPIX;
            const int n_vec = s_n[b];
            const int tb = b * TABV;

            ull acc0 = 0ull, acc1 = 0ull;
            for (int i = sl; i < n_vec; i += 8) {
                const int off = s_off[tb + i];
                ulonglong2 wp = *(const ulonglong2*)&s_w4[tb + i];
                ulonglong2 v0 = *(const ulonglong2*)(xb0 + off);
                ulonglong2 v1 = *(const ulonglong2*)(xb1 + off);
                acc0 = ffma2(wp.x, v0.x, acc0);
                acc0 = ffma2(wp.y, v0.y, acc0);
                acc1 = ffma2(wp.x, v1.x, acc1);
                acc1 = ffma2(wp.y, v1.y, acc1);
            }
            // 8-lane butterfly (all 4 subgroups reduce in the same instrs)
            #pragma unroll
            for (int sh = 4; sh; sh >>= 1) {
                acc0 = fadd2(acc0, __shfl_xor_sync(0xffffffffu, acc0, sh));
                acc1 = fadd2(acc1, __shfl_xor_sync(0xffffffffu, acc1, sh));
            }
            if (sl == 0) {
                g_featp[c + 0] = dup2(hsum2(acc0));
                g_featp[c + 1] = dup2(hsum2(acc1));
            }
        }
    }

    grid_sync(1);

    // ======== phase 1: GEMM 1 ========
    gemm_phase(s_dyn, g_featp, w1, &g_p1[0][0]);

    grid_sync(0);

    // ======== phase 2: combine partials + bias + relu + pack ========
    {
        const int s0 = bid * CHUNK;
        const int e0 = min(s0 + CHUNK, BB * HID);
        for (int idx = s0 + t; idx < e0; idx += NT) {
            const int c = idx % HID;
            float v = b1[c];
            #pragma unroll
            for (int z = 0; z < KSPL; z++) v += g_p1[z][idx];
            g_actp[idx] = dup2(fmaxf(v, 0.f));
        }
    }

    grid_sync(1);

    // ======== phase 3: GEMM 2 ========
    gemm_phase(s_dyn, g_actp, w2, &g_p2[0][0]);

    grid_sync(0);

    // ======== phase 4: final combine + dot(w3) ========
    if (bid < BB) {
        float acc = 0.f;
        for (int k = t; k < HID; k += NT) {
            const int idx = bid * HID + k;
            float v = b2[k];
            #pragma unroll
            for (int z = 0; z < KSPL; z++) v += g_p2[z][idx];
            acc = fmaf(fmaxf(v, 0.f), w3[k], acc);
        }
        #pragma unroll
        for (int sh = 16; sh; sh >>= 1) acc += __shfl_xor_sync(0xffffffffu, acc, sh);
        if (lane == 0) s_red[wid] = acc;
        __syncthreads();
        if (t == 0) {
            float r = 0.f;
            #pragma unroll
            for (int j = 0; j < 16; j++) r += s_red[j];
            out[bid] = r + b3[0];
        }
    }
}

// ---------------- launch ----------------
extern "C" void kernel_launch(void* const* d_in, const int* in_sizes, int n_in,
                              void* d_out, int out_size) {
    const float* X  = (const float*)d_in[0];
    const float* sb = (const float*)d_in[1];
    const float* w1 = (const float*)d_in[2];
    const float* b1 = (const float*)d_in[3];
    const float* w2 = (const float*)d_in[4];
    const float* b2 = (const float*)d_in[5];
    const float* w3 = (const float*)d_in[6];
    const float* b3 = (const float*)d_in[7];
    float* out = (float*)d_out;

    const int smem = BB * TABV * 16 + BB * TABV * 4;   // 102400 B
    static int configured = 0;
    if (!configured) {
        cudaFuncSetAttribute(fused_kernel,
                             cudaFuncAttributeMaxDynamicSharedMemorySize, smem);
        configured = 1;
    }
    fused_kernel<<<NB, NT, smem>>>(X, sb, w1, b1, w2, b2, w3, b3, out);
}